// round 2
// baseline (speedup 1.0000x reference)
#include <cuda_runtime.h>
#include <cuda_bf16.h>
#include <cstddef>

#define NN 50000
#define EE 800000
#define DF 128            // feature dim for x / hidden
#define KTOT 256          // GEMM K = 2*128

// ---------------- device scratch (static, no allocation) ----------------
__device__ int   g_cnt[NN];            // histogram, then fill-cursor
__device__ int   g_offs[NN + 1];       // CSR row offsets
__device__ int   g_col[EE];            // CSR col (src node)
__device__ float g_w[EE];              // CSR edge weight
__device__ float g_agg[(size_t)NN * DF];
__device__ float g_h1 [(size_t)NN * DF];
__device__ float g_h2 [(size_t)NN * DF];

// ---------------- CSR build ----------------
__global__ void zero_cnt_kernel() {
    int i = blockIdx.x * blockDim.x + threadIdx.x;
    if (i < NN) g_cnt[i] = 0;
}

__global__ void hist_kernel(const int* __restrict__ row) {
    int e = blockIdx.x * blockDim.x + threadIdx.x;
    if (e < EE) atomicAdd(&g_cnt[row[e]], 1);
}

// single-block scan of 50000 counts -> offsets; also primes cursor (= offsets)
__global__ void scan_kernel() {
    __shared__ int s[1024];
    const int tid = threadIdx.x;
    const int CH = (NN + 1023) / 1024;     // 49
    const int base = tid * CH;
    int sum = 0;
    for (int i = 0; i < CH; i++) {
        int idx = base + i;
        if (idx < NN) sum += g_cnt[idx];
    }
    s[tid] = sum;
    __syncthreads();
    // Hillis-Steele inclusive scan over 1024 partials
    for (int off = 1; off < 1024; off <<= 1) {
        int v = (tid >= off) ? s[tid - off] : 0;
        __syncthreads();
        s[tid] += v;
        __syncthreads();
    }
    int run = (tid == 0) ? 0 : s[tid - 1];
    for (int i = 0; i < CH; i++) {
        int idx = base + i;
        if (idx < NN) {
            g_offs[idx] = run;
            int c = g_cnt[idx];
            g_cnt[idx] = run;              // cursor for fill
            run += c;
        }
    }
    if (tid == 1023) g_offs[NN] = s[1023]; // == EE
}

__global__ void fill_kernel(const int* __restrict__ row, const int* __restrict__ col,
                            const float* __restrict__ ew) {
    int e = blockIdx.x * blockDim.x + threadIdx.x;
    if (e < EE) {
        int r = row[e];
        int p = atomicAdd(&g_cnt[r], 1);
        g_col[p] = col[e];
        g_w[p]   = ew[e];
    }
}

// ---------------- aggregation: one warp per node ----------------
// agg[n] = (sum_e w_e * x[col_e]) / max(sum_e w_e, 1)
__global__ __launch_bounds__(256) void agg_kernel(const float* __restrict__ xin) {
    int gw   = (blockIdx.x * blockDim.x + threadIdx.x) >> 5;
    int lane = threadIdx.x & 31;
    if (gw >= NN) return;
    int s = g_offs[gw], e = g_offs[gw + 1];
    float4 acc = make_float4(0.f, 0.f, 0.f, 0.f);
    float deg = 0.f;
    #pragma unroll 2
    for (int i = s; i < e; i++) {
        int   c = __ldg(&g_col[i]);
        float w = __ldg(&g_w[i]);
        float4 v = __ldg(((const float4*)(xin + (size_t)c * DF)) + lane);
        acc.x = fmaf(w, v.x, acc.x);
        acc.y = fmaf(w, v.y, acc.y);
        acc.z = fmaf(w, v.z, acc.z);
        acc.w = fmaf(w, v.w, acc.w);
        deg += w;
    }
    float inv = 1.f / fmaxf(deg, 1.f);
    float4* o = (float4*)(g_agg + (size_t)gw * DF);
    o[lane] = make_float4(acc.x * inv, acc.y * inv, acc.z * inv, acc.w * inv);
}

// ---------------- fused concat-GEMM: out = relu?([xin | g_agg] @ W.T + b) ----------------
// W: [BN, 256] row-major. BM=128, BK=16, 256 threads, thread tile 8 x (BN/16).
template<int BN, int RELU>
__global__ __launch_bounds__(256) void gemm_kernel(const float* __restrict__ xin,
                                                   const float* __restrict__ W,
                                                   const float* __restrict__ b,
                                                   float* __restrict__ out) {
    const int BM = 128, BK = 16;
    const int TN = BN / 16;                // 8 (BN=128) or 4 (BN=64)
    __shared__ float As[BK][BM + 1];
    __shared__ float Bs[BK][BN + 1];

    const int tid = threadIdx.x;
    const int m0  = blockIdx.x * BM;
    const int tr  = tid >> 4;              // 0..15 (row group)
    const int tc  = tid & 15;              // 0..15 (col group)

    float acc[8][TN];
    #pragma unroll
    for (int i = 0; i < 8; i++)
        #pragma unroll
        for (int j = 0; j < TN; j++) acc[i][j] = 0.f;

    for (int kt = 0; kt < KTOT; kt += BK) {
        const float* A = (kt < DF) ? xin : g_agg;   // concat([x, agg]) along K
        const int kk = kt & (DF - 1);

        // load A tile: 128 rows x 16 k = 512 float4, 2 per thread; store transposed
        #pragma unroll
        for (int it = 0; it < 2; it++) {
            int idx = tid + it * 256;
            int m = idx >> 2, q = idx & 3;
            int gm = m0 + m;
            float4 v = make_float4(0.f, 0.f, 0.f, 0.f);
            if (gm < NN)
                v = __ldg(((const float4*)(A + (size_t)gm * DF + kk)) + q);
            As[q * 4 + 0][m] = v.x;
            As[q * 4 + 1][m] = v.y;
            As[q * 4 + 2][m] = v.z;
            As[q * 4 + 3][m] = v.w;
        }
        // load B tile: Bs[k][j] = W[j*256 + kt + k]
        #pragma unroll
        for (int idx = tid; idx < BN * 4; idx += 256) {
            int j = idx >> 2, q = idx & 3;
            float4 v = __ldg(((const float4*)(W + (size_t)j * KTOT + kt)) + q);
            Bs[q * 4 + 0][j] = v.x;
            Bs[q * 4 + 1][j] = v.y;
            Bs[q * 4 + 2][j] = v.z;
            Bs[q * 4 + 3][j] = v.w;
        }
        __syncthreads();

        #pragma unroll
        for (int k = 0; k < BK; k++) {
            float ra[8], rb[TN];
            #pragma unroll
            for (int i = 0; i < 8; i++) ra[i] = As[k][tr * 8 + i];
            #pragma unroll
            for (int j = 0; j < TN; j++) rb[j] = Bs[k][tc * TN + j];
            #pragma unroll
            for (int i = 0; i < 8; i++)
                #pragma unroll
                for (int j = 0; j < TN; j++)
                    acc[i][j] = fmaf(ra[i], rb[j], acc[i][j]);
        }
        __syncthreads();
    }

    // epilogue: bias (+relu), write [NN, BN]
    float bias[TN];
    #pragma unroll
    for (int j = 0; j < TN; j++) bias[j] = __ldg(&b[tc * TN + j]);
    #pragma unroll
    for (int i = 0; i < 8; i++) {
        int gm = m0 + tr * 8 + i;
        if (gm < NN) {
            #pragma unroll
            for (int j = 0; j < TN; j++) {
                float v = acc[i][j] + bias[j];
                if (RELU) v = fmaxf(v, 0.f);
                out[(size_t)gm * BN + tc * TN + j] = v;
            }
        }
    }
}

// ---------------- launch ----------------
extern "C" void kernel_launch(void* const* d_in, const int* in_sizes, int n_in,
                              void* d_out, int out_size) {
    const float* x  = (const float*)d_in[0];
    const int*   ei = (const int*)  d_in[1];
    const float* ew = (const float*)d_in[2];
    const float* W0 = (const float*)d_in[3];
    const float* b0 = (const float*)d_in[4];
    const float* W1 = (const float*)d_in[5];
    const float* b1 = (const float*)d_in[6];
    const float* W2 = (const float*)d_in[7];
    const float* b2 = (const float*)d_in[8];
    float* out = (float*)d_out;

    const int* row = ei;        // edge_index[0] = dst
    const int* col = ei + EE;   // edge_index[1] = src

    static float* h1p = nullptr;
    static float* h2p = nullptr;
    if (!h1p) {
        cudaGetSymbolAddress((void**)&h1p, g_h1);
        cudaGetSymbolAddress((void**)&h2p, g_h2);
    }

    // CSR build (per call — timed, but cheap)
    zero_cnt_kernel<<<(NN + 255) / 256, 256>>>();
    hist_kernel<<<(EE + 255) / 256, 256>>>(row);
    scan_kernel<<<1, 1024>>>();
    fill_kernel<<<(EE + 255) / 256, 256>>>(row, col, ew);

    const int aggBlocks  = (NN * 32 + 255) / 256;    // one warp per node
    const int gemmBlocks = (NN + 127) / 128;

    // layer 0: x -> h1 (relu)
    agg_kernel<<<aggBlocks, 256>>>(x);
    gemm_kernel<128, 1><<<gemmBlocks, 256>>>(x, W0, b0, h1p);

    // layer 1: h1 -> h2 (relu)
    agg_kernel<<<aggBlocks, 256>>>(h1p);
    gemm_kernel<128, 1><<<gemmBlocks, 256>>>(h1p, W1, b1, h2p);

    // layer 2: h2 -> out (no relu, 64 cols)
    agg_kernel<<<aggBlocks, 256>>>(h2p);
    gemm_kernel<64, 0><<<gemmBlocks, 256>>>(h2p, W2, b2, out);
}

// round 4
// speedup vs baseline: 1.8305x; 1.8305x over previous
#include <cuda_runtime.h>
#include <cuda_bf16.h>
#include <cstdint>
#include <cstddef>

#define NN 50000
#define EE 800000
#define DF 128            // feature dim for x / hidden
#define KTOT 256          // GEMM K = 2*128

// ---------------- device scratch (static, no allocation) ----------------
__device__ int   g_cnt[NN];            // histogram, then fill-cursor
__device__ int   g_offs[NN + 1];       // CSR row offsets
__device__ int   g_col[EE];            // CSR col (src node)
__device__ float g_w[EE];              // CSR edge weight
__device__ float g_agg[(size_t)NN * DF];
__device__ float g_h1 [(size_t)NN * DF];
__device__ float g_h2 [(size_t)NN * DF];

// ---------------- CSR build ----------------
__global__ void zero_cnt_kernel() {
    int i = blockIdx.x * blockDim.x + threadIdx.x;
    if (i < NN) g_cnt[i] = 0;
}

__global__ void hist_kernel(const int* __restrict__ row) {
    int e = blockIdx.x * blockDim.x + threadIdx.x;
    if (e < EE) atomicAdd(&g_cnt[row[e]], 1);
}

// single-block scan of 50000 counts -> offsets; also primes cursor (= offsets)
__global__ void scan_kernel() {
    __shared__ int s[1024];
    const int tid = threadIdx.x;
    const int CH = (NN + 1023) / 1024;     // 49
    const int base = tid * CH;
    int sum = 0;
    for (int i = 0; i < CH; i++) {
        int idx = base + i;
        if (idx < NN) sum += g_cnt[idx];
    }
    s[tid] = sum;
    __syncthreads();
    for (int off = 1; off < 1024; off <<= 1) {
        int v = (tid >= off) ? s[tid - off] : 0;
        __syncthreads();
        s[tid] += v;
        __syncthreads();
    }
    int run = (tid == 0) ? 0 : s[tid - 1];
    for (int i = 0; i < CH; i++) {
        int idx = base + i;
        if (idx < NN) {
            g_offs[idx] = run;
            int c = g_cnt[idx];
            g_cnt[idx] = run;              // cursor for fill
            run += c;
        }
    }
    if (tid == 1023) g_offs[NN] = s[1023]; // == EE
}

__global__ void fill_kernel(const int* __restrict__ row, const int* __restrict__ col,
                            const float* __restrict__ ew) {
    int e = blockIdx.x * blockDim.x + threadIdx.x;
    if (e < EE) {
        int r = row[e];
        int p = atomicAdd(&g_cnt[r], 1);
        g_col[p] = col[e];
        g_w[p]   = ew[e];
    }
}

// ---------------- aggregation: one warp per node ----------------
__global__ __launch_bounds__(256) void agg_kernel(const float* __restrict__ xin) {
    int gw   = (blockIdx.x * blockDim.x + threadIdx.x) >> 5;
    int lane = threadIdx.x & 31;
    if (gw >= NN) return;
    int s = g_offs[gw], e = g_offs[gw + 1];
    float4 acc = make_float4(0.f, 0.f, 0.f, 0.f);
    float deg = 0.f;
    #pragma unroll 2
    for (int i = s; i < e; i++) {
        int   c = __ldg(&g_col[i]);
        float w = __ldg(&g_w[i]);
        float4 v = __ldg(((const float4*)(xin + (size_t)c * DF)) + lane);
        acc.x = fmaf(w, v.x, acc.x);
        acc.y = fmaf(w, v.y, acc.y);
        acc.z = fmaf(w, v.z, acc.z);
        acc.w = fmaf(w, v.w, acc.w);
        deg += w;
    }
    float inv = 1.f / fmaxf(deg, 1.f);
    float4* o = (float4*)(g_agg + (size_t)gw * DF);
    o[lane] = make_float4(acc.x * inv, acc.y * inv, acc.z * inv, acc.w * inv);
}

// ---------------- tf32 helpers ----------------
__device__ __forceinline__ float tf32_rna(float x) {
    uint32_t r;
    asm("cvt.rna.tf32.f32 %0, %1;" : "=r"(r) : "f"(x));
    return __uint_as_float(r);
}

__device__ __forceinline__ void mma_tf32(float* d, const uint32_t* a, uint32_t b0, uint32_t b1) {
    asm volatile(
        "mma.sync.aligned.m16n8k8.row.col.f32.tf32.tf32.f32 "
        "{%0,%1,%2,%3}, {%4,%5,%6,%7}, {%8,%9}, {%0,%1,%2,%3};\n"
        : "+f"(d[0]), "+f"(d[1]), "+f"(d[2]), "+f"(d[3])
        : "r"(a[0]), "r"(a[1]), "r"(a[2]), "r"(a[3]), "r"(b0), "r"(b1));
}

// ---------------- fused concat-GEMM (tf32 tensor cores) ----------------
// out = relu?([xin | g_agg] @ W.T + b).  W: [BN, 256] row-major.
// BM=128, BK=32, 256 threads = 8 warps in 4(M) x 2(N) grid, warp tile 32 x BN/2.
template<int BN, int RELU>
__global__ __launch_bounds__(256) void gemm_tf32(const float* __restrict__ xin,
                                                 const float* __restrict__ W,
                                                 const float* __restrict__ bias,
                                                 float* __restrict__ out) {
    const int BM = 128, BK = 32;
    const int NATN = BN / 16;                 // atoms per warp in N (8 or 4)
    const int SS = BK + 4;                    // smem stride (36 floats)
    __shared__ float As[BM][SS];
    __shared__ float Bs[BN][SS];

    const int tid  = threadIdx.x;
    const int lane = tid & 31;
    const int w    = tid >> 5;
    const int g    = lane >> 2;               // groupID (0..7)
    const int t4   = lane & 3;                // threadID_in_group (0..3)
    const int wm   = (w & 3) * 32;            // warp M offset in tile
    const int wn   = (w >> 2) * (BN / 2);     // warp N offset in tile
    const int m0   = blockIdx.x * BM;

    float acc[2][NATN][4];
    #pragma unroll
    for (int i = 0; i < 2; i++)
        #pragma unroll
        for (int j = 0; j < NATN; j++)
            #pragma unroll
            for (int q = 0; q < 4; q++) acc[i][j][q] = 0.f;

    for (int kt = 0; kt < KTOT; kt += BK) {
        const float* A = (kt < DF) ? xin : g_agg;   // concat([x, agg]) along K
        const int kk = kt & (DF - 1);

        // A tile: 128 rows x 32 k. 1024 float4 -> 4 per thread, coalesced.
        #pragma unroll
        for (int it = 0; it < 4; it++) {
            int idx = tid + it * 256;
            int m = idx >> 3, q = idx & 7;
            int gm = m0 + m;
            float4 v = make_float4(0.f, 0.f, 0.f, 0.f);
            if (gm < NN)
                v = __ldg(((const float4*)(A + (size_t)gm * DF + kk)) + q);
            As[m][q * 4 + 0] = tf32_rna(v.x);
            As[m][q * 4 + 1] = tf32_rna(v.y);
            As[m][q * 4 + 2] = tf32_rna(v.z);
            As[m][q * 4 + 3] = tf32_rna(v.w);
        }
        // B tile: BN rows x 32 k
        #pragma unroll
        for (int it = 0; it < BN / 32; it++) {
            int idx = tid + it * 256;
            int j = idx >> 3, q = idx & 7;
            float4 v = __ldg(((const float4*)(W + (size_t)j * KTOT + kt)) + q);
            Bs[j][q * 4 + 0] = tf32_rna(v.x);
            Bs[j][q * 4 + 1] = tf32_rna(v.y);
            Bs[j][q * 4 + 2] = tf32_rna(v.z);
            Bs[j][q * 4 + 3] = tf32_rna(v.w);
        }
        __syncthreads();

        #pragma unroll
        for (int ks = 0; ks < 4; ks++) {
            const int k0 = ks * 8;
            uint32_t af[2][4];
            #pragma unroll
            for (int ma = 0; ma < 2; ma++) {
                int r = wm + ma * 16 + g;
                af[ma][0] = __float_as_uint(As[r    ][k0 + t4    ]);
                af[ma][1] = __float_as_uint(As[r + 8][k0 + t4    ]);
                af[ma][2] = __float_as_uint(As[r    ][k0 + t4 + 4]);
                af[ma][3] = __float_as_uint(As[r + 8][k0 + t4 + 4]);
            }
            #pragma unroll
            for (int na = 0; na < NATN; na++) {
                int c = wn + na * 8 + g;
                uint32_t b0 = __float_as_uint(Bs[c][k0 + t4    ]);
                uint32_t b1 = __float_as_uint(Bs[c][k0 + t4 + 4]);
                #pragma unroll
                for (int ma = 0; ma < 2; ma++)
                    mma_tf32(acc[ma][na], af[ma], b0, b1);
            }
        }
        __syncthreads();
    }

    // epilogue: bias (+relu), write [NN, BN]
    #pragma unroll
    for (int na = 0; na < NATN; na++) {
        int col = wn + na * 8 + 2 * t4;
        float2 bb = *(const float2*)&bias[col];
        #pragma unroll
        for (int ma = 0; ma < 2; ma++) {
            int r0 = m0 + wm + ma * 16 + g;
            float2 v0 = make_float2(acc[ma][na][0] + bb.x, acc[ma][na][1] + bb.y);
            float2 v1 = make_float2(acc[ma][na][2] + bb.x, acc[ma][na][3] + bb.y);
            if (RELU) {
                v0.x = fmaxf(v0.x, 0.f); v0.y = fmaxf(v0.y, 0.f);
                v1.x = fmaxf(v1.x, 0.f); v1.y = fmaxf(v1.y, 0.f);
            }
            if (r0 < NN)     *(float2*)&out[(size_t)r0 * BN + col]       = v0;
            if (r0 + 8 < NN) *(float2*)&out[(size_t)(r0 + 8) * BN + col] = v1;
        }
    }
}

// ---------------- launch ----------------
extern "C" void kernel_launch(void* const* d_in, const int* in_sizes, int n_in,
                              void* d_out, int out_size) {
    const float* x  = (const float*)d_in[0];
    const int*   ei = (const int*)  d_in[1];
    const float* ew = (const float*)d_in[2];
    const float* W0 = (const float*)d_in[3];
    const float* b0 = (const float*)d_in[4];
    const float* W1 = (const float*)d_in[5];
    const float* b1 = (const float*)d_in[6];
    const float* W2 = (const float*)d_in[7];
    const float* b2 = (const float*)d_in[8];
    float* out = (float*)d_out;

    const int* row = ei;        // edge_index[0] = dst
    const int* col = ei + EE;   // edge_index[1] = src

    static float* h1p = nullptr;
    static float* h2p = nullptr;
    if (!h1p) {
        cudaGetSymbolAddress((void**)&h1p, g_h1);
        cudaGetSymbolAddress((void**)&h2p, g_h2);
    }

    // CSR build (per call)
    zero_cnt_kernel<<<(NN + 255) / 256, 256>>>();
    hist_kernel<<<(EE + 255) / 256, 256>>>(row);
    scan_kernel<<<1, 1024>>>();
    fill_kernel<<<(EE + 255) / 256, 256>>>(row, col, ew);

    const int aggBlocks  = (NN * 32 + 255) / 256;    // one warp per node
    const int gemmBlocks = (NN + 127) / 128;

    // layer 0: x -> h1 (relu)
    agg_kernel<<<aggBlocks, 256>>>(x);
    gemm_tf32<128, 1><<<gemmBlocks, 256>>>(x, W0, b0, h1p);

    // layer 1: h1 -> h2 (relu)
    agg_kernel<<<aggBlocks, 256>>>(h1p);
    gemm_tf32<128, 1><<<gemmBlocks, 256>>>(h1p, W1, b1, h2p);

    // layer 2: h2 -> out (no relu, 64 cols)
    agg_kernel<<<aggBlocks, 256>>>(h2p);
    gemm_tf32<64, 0><<<gemmBlocks, 256>>>(h2p, W2, b2, out);
}